// round 2
// baseline (speedup 1.0000x reference)
#include <cuda_runtime.h>

// Problem constants
#define Bb    2
#define Ss    2048
#define Hh    1024
#define NHEAD 16
#define HDIM  64
#define Mtot  (Bb*Ss)   // 4096

// Scratch (device globals: no allocation allowed)
__device__ float g_q[Mtot*Hh];
__device__ float g_k[Mtot*Hh];
__device__ float g_v[Mtot*Hh];
__device__ float g_o[Mtot*Hh];

__device__ __forceinline__ unsigned f2tf(float x){
    unsigned u; asm("cvt.rna.tf32.f32 %0, %1;" : "=r"(u) : "f"(x)); return u;
}
__device__ __forceinline__ float f2tf_f(float x){ return __uint_as_float(f2tf(x)); }

__device__ __forceinline__ void mma8(float* c, const unsigned* a, const unsigned* b){
    asm volatile("mma.sync.aligned.m16n8k8.row.col.f32.tf32.tf32.f32 "
        "{%0,%1,%2,%3}, {%4,%5,%6,%7}, {%8,%9}, {%0,%1,%2,%3};\n"
        : "+f"(c[0]), "+f"(c[1]), "+f"(c[2]), "+f"(c[3])
        : "r"(a[0]), "r"(a[1]), "r"(a[2]), "r"(a[3]), "r"(b[0]), "r"(b[1]));
}

// ---------------------------------------------------------------------------
// TF32 GEMM body: C[M=4096, N=1024] = A[4096,1024] @ W[1024,1024] + bias
// Block tile 128x128, BK=16, 256 threads (8 warps as 2(m) x 4(n), warp 64x32).
// ---------------------------------------------------------------------------
__device__ __forceinline__ void gemm_body(
    const float* __restrict__ A, const float* __restrict__ W,
    const float* __restrict__ bias, float* __restrict__ C)
{
    const int N = 1024, K = 1024;
    __shared__ float As[16][136];   // As[k][m], pad 8 -> conflict-free frag loads
    __shared__ float Bs[16][136];   // Bs[k][n]

    int tid  = threadIdx.x;
    int lane = tid & 31, warp = tid >> 5;
    int g = lane >> 2, tg = lane & 3;
    int wm = (warp & 1) * 64;
    int wn = (warp >> 1) * 32;
    int row0 = blockIdx.y * 128;
    int col0 = blockIdx.x * 128;

    float acc[4][4][4];
    #pragma unroll
    for (int mi = 0; mi < 4; mi++)
        #pragma unroll
        for (int ni = 0; ni < 4; ni++)
            #pragma unroll
            for (int r = 0; r < 4; r++) acc[mi][ni][r] = 0.f;

    for (int k0 = 0; k0 < K; k0 += 16) {
        #pragma unroll
        for (int j = 0; j < 2; j++) {
            int idx = tid + 256*j;
            // A tile: 128 rows x 16 cols
            int ra = idx >> 2;           // 0..127
            int kq = (idx & 3) << 2;     // 0,4,8,12
            float4 va = *reinterpret_cast<const float4*>(A + (size_t)(row0+ra)*K + k0 + kq);
            As[kq+0][ra] = f2tf_f(va.x);
            As[kq+1][ra] = f2tf_f(va.y);
            As[kq+2][ra] = f2tf_f(va.z);
            As[kq+3][ra] = f2tf_f(va.w);
            // B tile: 16 rows x 128 cols
            int rb = idx >> 5;           // 0..15
            int nq = (idx & 31) << 2;    // 0..124
            float4 vb = *reinterpret_cast<const float4*>(W + (size_t)(k0+rb)*N + col0 + nq);
            Bs[rb][nq+0] = f2tf_f(vb.x);
            Bs[rb][nq+1] = f2tf_f(vb.y);
            Bs[rb][nq+2] = f2tf_f(vb.z);
            Bs[rb][nq+3] = f2tf_f(vb.w);
        }
        __syncthreads();

        #pragma unroll
        for (int ks = 0; ks < 2; ks++) {
            int kk = ks * 8;
            unsigned a[4][4], b[4][2];
            #pragma unroll
            for (int mi = 0; mi < 4; mi++) {
                int m = wm + mi*16;
                a[mi][0] = __float_as_uint(As[kk+tg  ][m+g  ]);
                a[mi][1] = __float_as_uint(As[kk+tg  ][m+g+8]);
                a[mi][2] = __float_as_uint(As[kk+tg+4][m+g  ]);
                a[mi][3] = __float_as_uint(As[kk+tg+4][m+g+8]);
            }
            #pragma unroll
            for (int ni = 0; ni < 4; ni++) {
                int n = wn + ni*8;
                b[ni][0] = __float_as_uint(Bs[kk+tg  ][n+g]);
                b[ni][1] = __float_as_uint(Bs[kk+tg+4][n+g]);
            }
            #pragma unroll
            for (int mi = 0; mi < 4; mi++)
                #pragma unroll
                for (int ni = 0; ni < 4; ni++)
                    mma8(acc[mi][ni], a[mi], b[ni]);
        }
        __syncthreads();
    }

    #pragma unroll
    for (int mi = 0; mi < 4; mi++) {
        int r = row0 + wm + mi*16 + g;
        #pragma unroll
        for (int ni = 0; ni < 4; ni++) {
            int c = col0 + wn + ni*8 + 2*tg;
            float b0 = bias[c], b1 = bias[c+1];
            C[(size_t)r*N + c]       = acc[mi][ni][0] + b0;
            C[(size_t)r*N + c+1]     = acc[mi][ni][1] + b1;
            C[(size_t)(r+8)*N + c]   = acc[mi][ni][2] + b0;
            C[(size_t)(r+8)*N + c+1] = acc[mi][ni][3] + b1;
        }
    }
}

// Fused Q/K/V projections via grid.z
__global__ __launch_bounds__(256)
void proj3_kernel(const float* __restrict__ q, const float* __restrict__ k,
                  const float* __restrict__ v,
                  const float* __restrict__ wq, const float* __restrict__ bq,
                  const float* __restrict__ wk, const float* __restrict__ bk,
                  const float* __restrict__ wv, const float* __restrict__ bv)
{
    if (blockIdx.z == 0)      gemm_body(q, wq, bq, g_q);
    else if (blockIdx.z == 1) gemm_body(k, wk, bk, g_k);
    else                      gemm_body(v, wv, bv, g_v);
}

__global__ __launch_bounds__(256)
void out_kernel(const float* __restrict__ wo, const float* __restrict__ bo,
                float* __restrict__ out)
{
    gemm_body(g_o, wo, bo, out);
}

// ---------------------------------------------------------------------------
// Flash attention: grid (32 q-tiles, 32 b*h). Block 128 threads (4 warps),
// each warp owns 16 q-rows. K/V tiles of 64 staged via smem, TF32 MMA.
// logits = (Q.K)/64 + (1-mask)*(-1e10/8); softmax online; O = P.V / l.
// ---------------------------------------------------------------------------
#define ATTN_SMEM_FLOATS (3*64*68 + 64)

__global__ __launch_bounds__(128)
void attn_kernel(const float* __restrict__ mask)
{
    extern __shared__ float sm[];
    float* Qs  = sm;               // 64x68, later reused as Ps
    float* Ks  = sm + 64*68;       // 64x68  [kpos][d]
    float* Vs  = sm + 2*64*68;     // 64x68  [kpos][d]
    float* msk = sm + 3*64*68;     // 64

    int tid = threadIdx.x, lane = tid & 31, warp = tid >> 5;
    int g = lane >> 2, tg = lane & 3;
    int q0 = blockIdx.x * 64;
    int b  = blockIdx.y >> 4, h = blockIdx.y & 15;
    int wrow = warp * 16;

    const float* Qg = g_q + (size_t)b*Ss*Hh + h*HDIM;
    const float* Kg = g_k + (size_t)b*Ss*Hh + h*HDIM;
    const float* Vg = g_v + (size_t)b*Ss*Hh + h*HDIM;
    const float* mrow = mask + (size_t)b*Ss;

    // Load Q tile, pre-scaled by 1/64 (both /SCALE divisions folded in)
    #pragma unroll
    for (int j = 0; j < 8; j++) {
        int idx = tid + 128*j;
        int r = idx >> 4, dq = (idx & 15) << 2;
        float4 v = *reinterpret_cast<const float4*>(Qg + (size_t)(q0+r)*Hh + dq);
        Qs[r*68 + dq+0] = f2tf_f(v.x * 0.015625f);
        Qs[r*68 + dq+1] = f2tf_f(v.y * 0.015625f);
        Qs[r*68 + dq+2] = f2tf_f(v.z * 0.015625f);
        Qs[r*68 + dq+3] = f2tf_f(v.w * 0.015625f);
    }
    __syncthreads();

    unsigned qa[8][4];
    #pragma unroll
    for (int kk = 0; kk < 8; kk++) {
        qa[kk][0] = __float_as_uint(Qs[(wrow+g  )*68 + kk*8+tg  ]);
        qa[kk][1] = __float_as_uint(Qs[(wrow+g+8)*68 + kk*8+tg  ]);
        qa[kk][2] = __float_as_uint(Qs[(wrow+g  )*68 + kk*8+tg+4]);
        qa[kk][3] = __float_as_uint(Qs[(wrow+g+8)*68 + kk*8+tg+4]);
    }
    __syncthreads();
    float* Ps = Qs;   // Q smem reused as P buffer

    float oc[8][4];
    #pragma unroll
    for (int ni = 0; ni < 8; ni++)
        #pragma unroll
        for (int r = 0; r < 4; r++) oc[ni][r] = 0.f;

    float m0 = -1e30f, m1 = -1e30f, l0 = 0.f, l1 = 0.f;

    for (int kt = 0; kt < 32; kt++) {
        // Stage K/V tiles (tf32) + mask slice
        #pragma unroll
        for (int j = 0; j < 8; j++) {
            int idx = tid + 128*j;
            int r = idx >> 4, dq = (idx & 15) << 2;
            float4 kv = *reinterpret_cast<const float4*>(Kg + (size_t)(kt*64+r)*Hh + dq);
            Ks[r*68 + dq+0] = f2tf_f(kv.x);
            Ks[r*68 + dq+1] = f2tf_f(kv.y);
            Ks[r*68 + dq+2] = f2tf_f(kv.z);
            Ks[r*68 + dq+3] = f2tf_f(kv.w);
            float4 vv = *reinterpret_cast<const float4*>(Vg + (size_t)(kt*64+r)*Hh + dq);
            Vs[r*68 + dq+0] = f2tf_f(vv.x);
            Vs[r*68 + dq+1] = f2tf_f(vv.y);
            Vs[r*68 + dq+2] = f2tf_f(vv.z);
            Vs[r*68 + dq+3] = f2tf_f(vv.w);
        }
        if (tid < 64) msk[tid] = mrow[kt*64 + tid];
        __syncthreads();

        // S = Qscaled . K^T   (warp: 16 rows x 64 cols)
        float sc[8][4];
        #pragma unroll
        for (int ni = 0; ni < 8; ni++)
            #pragma unroll
            for (int r = 0; r < 4; r++) sc[ni][r] = 0.f;
        #pragma unroll
        for (int kk = 0; kk < 8; kk++) {
            #pragma unroll
            for (int ni = 0; ni < 8; ni++) {
                unsigned bb[2];
                bb[0] = __float_as_uint(Ks[(ni*8+g)*68 + kk*8+tg  ]);
                bb[1] = __float_as_uint(Ks[(ni*8+g)*68 + kk*8+tg+4]);
                mma8(sc[ni], qa[kk], bb);
            }
        }
        // additive mask: (1-m)*(-1e10)/8
        #pragma unroll
        for (int ni = 0; ni < 8; ni++) {
            int c = ni*8 + 2*tg;
            float w0 = (1.0f - msk[c  ]) * (-1.25e9f);
            float w1 = (1.0f - msk[c+1]) * (-1.25e9f);
            sc[ni][0] += w0; sc[ni][1] += w1;
            sc[ni][2] += w0; sc[ni][3] += w1;
        }
        // Online softmax (rows g and g+8; reduce over tg lanes)
        float tm0 = -1e30f, tm1 = -1e30f;
        #pragma unroll
        for (int ni = 0; ni < 8; ni++) {
            tm0 = fmaxf(tm0, fmaxf(sc[ni][0], sc[ni][1]));
            tm1 = fmaxf(tm1, fmaxf(sc[ni][2], sc[ni][3]));
        }
        tm0 = fmaxf(tm0, __shfl_xor_sync(0xffffffffu, tm0, 1));
        tm0 = fmaxf(tm0, __shfl_xor_sync(0xffffffffu, tm0, 2));
        tm1 = fmaxf(tm1, __shfl_xor_sync(0xffffffffu, tm1, 1));
        tm1 = fmaxf(tm1, __shfl_xor_sync(0xffffffffu, tm1, 2));
        float nm0 = fmaxf(m0, tm0), nm1 = fmaxf(m1, tm1);
        float al0 = __expf(m0 - nm0), al1 = __expf(m1 - nm1);
        float rs0 = 0.f, rs1 = 0.f;
        #pragma unroll
        for (int ni = 0; ni < 8; ni++) {
            float p0 = __expf(sc[ni][0] - nm0);
            float p1 = __expf(sc[ni][1] - nm0);
            float p2 = __expf(sc[ni][2] - nm1);
            float p3 = __expf(sc[ni][3] - nm1);
            rs0 += p0 + p1; rs1 += p2 + p3;
            int c = ni*8 + 2*tg;
            Ps[(wrow+g  )*68 + c  ] = f2tf_f(p0);
            Ps[(wrow+g  )*68 + c+1] = f2tf_f(p1);
            Ps[(wrow+g+8)*68 + c  ] = f2tf_f(p2);
            Ps[(wrow+g+8)*68 + c+1] = f2tf_f(p3);
            oc[ni][0] *= al0; oc[ni][1] *= al0;
            oc[ni][2] *= al1; oc[ni][3] *= al1;
        }
        rs0 += __shfl_xor_sync(0xffffffffu, rs0, 1);
        rs0 += __shfl_xor_sync(0xffffffffu, rs0, 2);
        rs1 += __shfl_xor_sync(0xffffffffu, rs1, 1);
        rs1 += __shfl_xor_sync(0xffffffffu, rs1, 2);
        l0 = l0*al0 + rs0;  l1 = l1*al1 + rs1;
        m0 = nm0;  m1 = nm1;
        __syncwarp();

        // O += P . V  (each warp reads only its own P rows)
        #pragma unroll
        for (int kk = 0; kk < 8; kk++) {
            unsigned pa[4];
            pa[0] = __float_as_uint(Ps[(wrow+g  )*68 + kk*8+tg  ]);
            pa[1] = __float_as_uint(Ps[(wrow+g+8)*68 + kk*8+tg  ]);
            pa[2] = __float_as_uint(Ps[(wrow+g  )*68 + kk*8+tg+4]);
            pa[3] = __float_as_uint(Ps[(wrow+g+8)*68 + kk*8+tg+4]);
            #pragma unroll
            for (int ni = 0; ni < 8; ni++) {
                unsigned bb[2];
                bb[0] = __float_as_uint(Vs[(kk*8+tg  )*68 + ni*8+g]);
                bb[1] = __float_as_uint(Vs[(kk*8+tg+4)*68 + ni*8+g]);
                mma8(oc[ni], pa, bb);
            }
        }
        __syncthreads();   // protect Ks/Vs before next stage
    }

    float inv0 = 1.f / l0, inv1 = 1.f / l1;
    float* Og = g_o + (size_t)b*Ss*Hh + h*HDIM;
    #pragma unroll
    for (int ni = 0; ni < 8; ni++) {
        int c = ni*8 + 2*tg;
        int r = q0 + wrow + g;
        Og[(size_t)r*Hh + c]       = oc[ni][0] * inv0;
        Og[(size_t)r*Hh + c+1]     = oc[ni][1] * inv0;
        Og[(size_t)(r+8)*Hh + c]   = oc[ni][2] * inv1;
        Og[(size_t)(r+8)*Hh + c+1] = oc[ni][3] * inv1;
    }
}

// ---------------------------------------------------------------------------
extern "C" void kernel_launch(void* const* d_in, const int* in_sizes, int n_in,
                              void* d_out, int out_size)
{
    const float* query = (const float*)d_in[0];
    const float* key   = (const float*)d_in[1];
    const float* value = (const float*)d_in[2];
    const float* mask  = (const float*)d_in[3];
    const float* wq    = (const float*)d_in[4];
    const float* bq    = (const float*)d_in[5];
    const float* wk    = (const float*)d_in[6];
    const float* bk    = (const float*)d_in[7];
    const float* wv    = (const float*)d_in[8];
    const float* bv    = (const float*)d_in[9];
    const float* wo    = (const float*)d_in[10];
    const float* bo    = (const float*)d_in[11];

    const int attn_smem = ATTN_SMEM_FLOATS * (int)sizeof(float);  // 52480 B
    cudaFuncSetAttribute(attn_kernel, cudaFuncAttributeMaxDynamicSharedMemorySize, attn_smem);

    proj3_kernel<<<dim3(8, 32, 3), 256>>>(query, key, value, wq, bq, wk, bk, wv, bv);
    attn_kernel<<<dim3(32, 32), 128, attn_smem>>>(mask);
    out_kernel<<<dim3(8, 32), 256>>>(wo, bo, (float*)d_out);
}

// round 3
// speedup vs baseline: 1.5131x; 1.5131x over previous
#include <cuda_runtime.h>

// Problem constants
#define Bb    2
#define Ss    2048
#define Hh    1024
#define NHEAD 16
#define HDIM  64
#define Mtot  (Bb*Ss)   // 4096

// Scratch (device globals: no allocation allowed)
__device__ float g_q[Mtot*Hh];
__device__ float g_k[Mtot*Hh];
__device__ float g_v[Mtot*Hh];
__device__ float g_o[Mtot*Hh];

__device__ __forceinline__ unsigned f2tf(float x){
    unsigned u; asm("cvt.rna.tf32.f32 %0, %1;" : "=r"(u) : "f"(x)); return u;
}
__device__ __forceinline__ float f2tf_f(float x){ return __uint_as_float(f2tf(x)); }

__device__ __forceinline__ void mma8(float* c, const unsigned* a, const unsigned* b){
    asm volatile("mma.sync.aligned.m16n8k8.row.col.f32.tf32.tf32.f32 "
        "{%0,%1,%2,%3}, {%4,%5,%6,%7}, {%8,%9}, {%0,%1,%2,%3};\n"
        : "+f"(c[0]), "+f"(c[1]), "+f"(c[2]), "+f"(c[3])
        : "r"(a[0]), "r"(a[1]), "r"(a[2]), "r"(a[3]), "r"(b[0]), "r"(b[1]));
}

// ---------------------------------------------------------------------------
// TF32 GEMM body: C[M=4096, N=1024] = A[4096,1024] @ W[1024,1024] + bias
// Block tile 128x128, BK=16, 256 threads (8 warps as 2(m) x 4(n), warp 64x32).
// ---------------------------------------------------------------------------
__device__ __forceinline__ void gemm_body(
    const float* __restrict__ A, const float* __restrict__ W,
    const float* __restrict__ bias, float* __restrict__ C)
{
    const int N = 1024, K = 1024;
    __shared__ float As[16][136];   // As[k][m], pad 8 -> conflict-free frag loads
    __shared__ float Bs[16][136];   // Bs[k][n]

    int tid  = threadIdx.x;
    int lane = tid & 31, warp = tid >> 5;
    int g = lane >> 2, tg = lane & 3;
    int wm = (warp & 1) * 64;
    int wn = (warp >> 1) * 32;
    int row0 = blockIdx.y * 128;
    int col0 = blockIdx.x * 128;

    float acc[4][4][4];
    #pragma unroll
    for (int mi = 0; mi < 4; mi++)
        #pragma unroll
        for (int ni = 0; ni < 4; ni++)
            #pragma unroll
            for (int r = 0; r < 4; r++) acc[mi][ni][r] = 0.f;

    for (int k0 = 0; k0 < K; k0 += 16) {
        #pragma unroll
        for (int j = 0; j < 2; j++) {
            int idx = tid + 256*j;
            // A tile: 128 rows x 16 cols
            int ra = idx >> 2;           // 0..127
            int kq = (idx & 3) << 2;     // 0,4,8,12
            float4 va = *reinterpret_cast<const float4*>(A + (size_t)(row0+ra)*K + k0 + kq);
            As[kq+0][ra] = f2tf_f(va.x);
            As[kq+1][ra] = f2tf_f(va.y);
            As[kq+2][ra] = f2tf_f(va.z);
            As[kq+3][ra] = f2tf_f(va.w);
            // B tile: 16 rows x 128 cols
            int rb = idx >> 5;           // 0..15
            int nq = (idx & 31) << 2;    // 0..124
            float4 vb = *reinterpret_cast<const float4*>(W + (size_t)(k0+rb)*N + col0 + nq);
            Bs[rb][nq+0] = f2tf_f(vb.x);
            Bs[rb][nq+1] = f2tf_f(vb.y);
            Bs[rb][nq+2] = f2tf_f(vb.z);
            Bs[rb][nq+3] = f2tf_f(vb.w);
        }
        __syncthreads();

        #pragma unroll
        for (int ks = 0; ks < 2; ks++) {
            int kk = ks * 8;
            unsigned a[4][4], b[4][2];
            #pragma unroll
            for (int mi = 0; mi < 4; mi++) {
                int m = wm + mi*16;
                a[mi][0] = __float_as_uint(As[kk+tg  ][m+g  ]);
                a[mi][1] = __float_as_uint(As[kk+tg  ][m+g+8]);
                a[mi][2] = __float_as_uint(As[kk+tg+4][m+g  ]);
                a[mi][3] = __float_as_uint(As[kk+tg+4][m+g+8]);
            }
            #pragma unroll
            for (int ni = 0; ni < 4; ni++) {
                int n = wn + ni*8;
                b[ni][0] = __float_as_uint(Bs[kk+tg  ][n+g]);
                b[ni][1] = __float_as_uint(Bs[kk+tg+4][n+g]);
            }
            #pragma unroll
            for (int mi = 0; mi < 4; mi++)
                #pragma unroll
                for (int ni = 0; ni < 4; ni++)
                    mma8(acc[mi][ni], a[mi], b[ni]);
        }
        __syncthreads();
    }

    #pragma unroll
    for (int mi = 0; mi < 4; mi++) {
        int r = row0 + wm + mi*16 + g;
        #pragma unroll
        for (int ni = 0; ni < 4; ni++) {
            int c = col0 + wn + ni*8 + 2*tg;
            float b0 = bias[c], b1 = bias[c+1];
            C[(size_t)r*N + c]       = acc[mi][ni][0] + b0;
            C[(size_t)r*N + c+1]     = acc[mi][ni][1] + b1;
            C[(size_t)(r+8)*N + c]   = acc[mi][ni][2] + b0;
            C[(size_t)(r+8)*N + c+1] = acc[mi][ni][3] + b1;
        }
    }
}

// Fused Q/K/V projections via grid.z
__global__ __launch_bounds__(256)
void proj3_kernel(const float* __restrict__ q, const float* __restrict__ k,
                  const float* __restrict__ v,
                  const float* __restrict__ wq, const float* __restrict__ bq,
                  const float* __restrict__ wk, const float* __restrict__ bk,
                  const float* __restrict__ wv, const float* __restrict__ bv)
{
    if (blockIdx.z == 0)      gemm_body(q, wq, bq, g_q);
    else if (blockIdx.z == 1) gemm_body(k, wk, bk, g_k);
    else                      gemm_body(v, wv, bv, g_v);
}

__global__ __launch_bounds__(256)
void out_kernel(const float* __restrict__ wo, const float* __restrict__ bo,
                float* __restrict__ out)
{
    gemm_body(g_o, wo, bo, out);
}

// ---------------------------------------------------------------------------
// Flash attention: grid (32 q-tiles, 32 b*h). Block 128 threads (4 warps),
// each warp owns 16 q-rows. K/V tiles of 64 staged via smem, TF32 MMA.
// logits = (Q.K)/64 + (1-mask)*(-1e10/8); softmax online; O = P.V / l.
// ---------------------------------------------------------------------------
#define ATTN_SMEM_FLOATS (3*64*68 + 64)

__global__ __launch_bounds__(128)
void attn_kernel(const float* __restrict__ mask)
{
    extern __shared__ float sm[];
    float* Qs  = sm;               // 64x68, later reused as Ps
    float* Ks  = sm + 64*68;       // 64x68  [kpos][d]
    float* Vs  = sm + 2*64*68;     // 64x68  [kpos][d]
    float* msk = sm + 3*64*68;     // 64

    int tid = threadIdx.x, lane = tid & 31, warp = tid >> 5;
    int g = lane >> 2, tg = lane & 3;
    int q0 = blockIdx.x * 64;
    int b  = blockIdx.y >> 4, h = blockIdx.y & 15;
    int wrow = warp * 16;

    const float* Qg = g_q + (size_t)b*Ss*Hh + h*HDIM;
    const float* Kg = g_k + (size_t)b*Ss*Hh + h*HDIM;
    const float* Vg = g_v + (size_t)b*Ss*Hh + h*HDIM;
    const float* mrow = mask + (size_t)b*Ss;

    // Load Q tile, pre-scaled by 1/64 (both /SCALE divisions folded in)
    #pragma unroll
    for (int j = 0; j < 8; j++) {
        int idx = tid + 128*j;
        int r = idx >> 4, dq = (idx & 15) << 2;
        float4 v = *reinterpret_cast<const float4*>(Qg + (size_t)(q0+r)*Hh + dq);
        Qs[r*68 + dq+0] = f2tf_f(v.x * 0.015625f);
        Qs[r*68 + dq+1] = f2tf_f(v.y * 0.015625f);
        Qs[r*68 + dq+2] = f2tf_f(v.z * 0.015625f);
        Qs[r*68 + dq+3] = f2tf_f(v.w * 0.015625f);
    }
    __syncthreads();

    unsigned qa[8][4];
    #pragma unroll
    for (int kk = 0; kk < 8; kk++) {
        qa[kk][0] = __float_as_uint(Qs[(wrow+g  )*68 + kk*8+tg  ]);
        qa[kk][1] = __float_as_uint(Qs[(wrow+g+8)*68 + kk*8+tg  ]);
        qa[kk][2] = __float_as_uint(Qs[(wrow+g  )*68 + kk*8+tg+4]);
        qa[kk][3] = __float_as_uint(Qs[(wrow+g+8)*68 + kk*8+tg+4]);
    }
    __syncthreads();
    float* Ps = Qs;   // Q smem reused as P buffer

    float oc[8][4];
    #pragma unroll
    for (int ni = 0; ni < 8; ni++)
        #pragma unroll
        for (int r = 0; r < 4; r++) oc[ni][r] = 0.f;

    float m0 = -1e30f, m1 = -1e30f, l0 = 0.f, l1 = 0.f;

    for (int kt = 0; kt < 32; kt++) {
        // Stage K/V tiles (tf32) + mask slice
        #pragma unroll
        for (int j = 0; j < 8; j++) {
            int idx = tid + 128*j;
            int r = idx >> 4, dq = (idx & 15) << 2;
            float4 kv = *reinterpret_cast<const float4*>(Kg + (size_t)(kt*64+r)*Hh + dq);
            Ks[r*68 + dq+0] = f2tf_f(kv.x);
            Ks[r*68 + dq+1] = f2tf_f(kv.y);
            Ks[r*68 + dq+2] = f2tf_f(kv.z);
            Ks[r*68 + dq+3] = f2tf_f(kv.w);
            float4 vv = *reinterpret_cast<const float4*>(Vg + (size_t)(kt*64+r)*Hh + dq);
            Vs[r*68 + dq+0] = f2tf_f(vv.x);
            Vs[r*68 + dq+1] = f2tf_f(vv.y);
            Vs[r*68 + dq+2] = f2tf_f(vv.z);
            Vs[r*68 + dq+3] = f2tf_f(vv.w);
        }
        if (tid < 64) msk[tid] = mrow[kt*64 + tid];
        __syncthreads();

        // S = Qscaled . K^T   (warp: 16 rows x 64 cols)
        float sc[8][4];
        #pragma unroll
        for (int ni = 0; ni < 8; ni++)
            #pragma unroll
            for (int r = 0; r < 4; r++) sc[ni][r] = 0.f;
        #pragma unroll
        for (int kk = 0; kk < 8; kk++) {
            #pragma unroll
            for (int ni = 0; ni < 8; ni++) {
                unsigned bb[2];
                bb[0] = __float_as_uint(Ks[(ni*8+g)*68 + kk*8+tg  ]);
                bb[1] = __float_as_uint(Ks[(ni*8+g)*68 + kk*8+tg+4]);
                mma8(sc[ni], qa[kk], bb);
            }
        }
        // additive mask: (1-m)*(-1e10)/8
        #pragma unroll
        for (int ni = 0; ni < 8; ni++) {
            int c = ni*8 + 2*tg;
            float w0 = (1.0f - msk[c  ]) * (-1.25e9f);
            float w1 = (1.0f - msk[c+1]) * (-1.25e9f);
            sc[ni][0] += w0; sc[ni][1] += w1;
            sc[ni][2] += w0; sc[ni][3] += w1;
        }
        // Online softmax (rows g and g+8; reduce over tg lanes)
        float tm0 = -1e30f, tm1 = -1e30f;
        #pragma unroll
        for (int ni = 0; ni < 8; ni++) {
            tm0 = fmaxf(tm0, fmaxf(sc[ni][0], sc[ni][1]));
            tm1 = fmaxf(tm1, fmaxf(sc[ni][2], sc[ni][3]));
        }
        tm0 = fmaxf(tm0, __shfl_xor_sync(0xffffffffu, tm0, 1));
        tm0 = fmaxf(tm0, __shfl_xor_sync(0xffffffffu, tm0, 2));
        tm1 = fmaxf(tm1, __shfl_xor_sync(0xffffffffu, tm1, 1));
        tm1 = fmaxf(tm1, __shfl_xor_sync(0xffffffffu, tm1, 2));
        float nm0 = fmaxf(m0, tm0), nm1 = fmaxf(m1, tm1);
        float al0 = __expf(m0 - nm0), al1 = __expf(m1 - nm1);
        float rs0 = 0.f, rs1 = 0.f;
        #pragma unroll
        for (int ni = 0; ni < 8; ni++) {
            float p0 = __expf(sc[ni][0] - nm0);
            float p1 = __expf(sc[ni][1] - nm0);
            float p2 = __expf(sc[ni][2] - nm1);
            float p3 = __expf(sc[ni][3] - nm1);
            rs0 += p0 + p1; rs1 += p2 + p3;
            int c = ni*8 + 2*tg;
            Ps[(wrow+g  )*68 + c  ] = f2tf_f(p0);
            Ps[(wrow+g  )*68 + c+1] = f2tf_f(p1);
            Ps[(wrow+g+8)*68 + c  ] = f2tf_f(p2);
            Ps[(wrow+g+8)*68 + c+1] = f2tf_f(p3);
            oc[ni][0] *= al0; oc[ni][1] *= al0;
            oc[ni][2] *= al1; oc[ni][3] *= al1;
        }
        rs0 += __shfl_xor_sync(0xffffffffu, rs0, 1);
        rs0 += __shfl_xor_sync(0xffffffffu, rs0, 2);
        rs1 += __shfl_xor_sync(0xffffffffu, rs1, 1);
        rs1 += __shfl_xor_sync(0xffffffffu, rs1, 2);
        l0 = l0*al0 + rs0;  l1 = l1*al1 + rs1;
        m0 = nm0;  m1 = nm1;
        __syncwarp();

        // O += P . V  (each warp reads only its own P rows)
        #pragma unroll
        for (int kk = 0; kk < 8; kk++) {
            unsigned pa[4];
            pa[0] = __float_as_uint(Ps[(wrow+g  )*68 + kk*8+tg  ]);
            pa[1] = __float_as_uint(Ps[(wrow+g+8)*68 + kk*8+tg  ]);
            pa[2] = __float_as_uint(Ps[(wrow+g  )*68 + kk*8+tg+4]);
            pa[3] = __float_as_uint(Ps[(wrow+g+8)*68 + kk*8+tg+4]);
            #pragma unroll
            for (int ni = 0; ni < 8; ni++) {
                unsigned bb[2];
                bb[0] = __float_as_uint(Vs[(kk*8+tg  )*68 + ni*8+g]);
                bb[1] = __float_as_uint(Vs[(kk*8+tg+4)*68 + ni*8+g]);
                mma8(oc[ni], pa, bb);
            }
        }
        __syncthreads();   // protect Ks/Vs before next stage
    }

    float inv0 = 1.f / l0, inv1 = 1.f / l1;
    float* Og = g_o + (size_t)b*Ss*Hh + h*HDIM;
    #pragma unroll
    for (int ni = 0; ni < 8; ni++) {
        int c = ni*8 + 2*tg;
        int r = q0 + wrow + g;
        Og[(size_t)r*Hh + c]       = oc[ni][0] * inv0;
        Og[(size_t)r*Hh + c+1]     = oc[ni][1] * inv0;
        Og[(size_t)(r+8)*Hh + c]   = oc[ni][2] * inv1;
        Og[(size_t)(r+8)*Hh + c+1] = oc[ni][3] * inv1;
    }
}

// ---------------------------------------------------------------------------
extern "C" void kernel_launch(void* const* d_in, const int* in_sizes, int n_in,
                              void* d_out, int out_size)
{
    const float* query = (const float*)d_in[0];
    const float* key   = (const float*)d_in[1];
    const float* value = (const float*)d_in[2];
    const float* mask  = (const float*)d_in[3];
    const float* wq    = (const float*)d_in[4];
    const float* bq    = (const float*)d_in[5];
    const float* wk    = (const float*)d_in[6];
    const float* bk    = (const float*)d_in[7];
    const float* wv    = (const float*)d_in[8];
    const float* bv    = (const float*)d_in[9];
    const float* wo    = (const float*)d_in[10];
    const float* bo    = (const float*)d_in[11];

    const int attn_smem = ATTN_SMEM_FLOATS * (int)sizeof(float);  // 52480 B
    cudaFuncSetAttribute(attn_kernel, cudaFuncAttributeMaxDynamicSharedMemorySize, attn_smem);

    proj3_kernel<<<dim3(8, 32, 3), 256>>>(query, key, value, wq, bq, wk, bk, wv, bv);
    attn_kernel<<<dim3(32, 32), 128, attn_smem>>>(mask);
    out_kernel<<<dim3(8, 32), 256>>>(wo, bo, (float*)d_out);
}

// round 5
// speedup vs baseline: 1.6982x; 1.1223x over previous
#include <cuda_runtime.h>
#include <cstdint>

// Problem constants
#define Bb    2
#define Ss    2048
#define Hh    1024
#define NHEAD 16
#define HDIM  64
#define Mtot  (Bb*Ss)   // 4096

// Scratch (device globals: no allocation allowed)
__device__ float g_q[Mtot*Hh];
__device__ float g_k[Mtot*Hh];
__device__ float g_v[Mtot*Hh];
__device__ float g_o[Mtot*Hh];

__device__ __forceinline__ unsigned f2tf(float x){
    unsigned u; asm("cvt.rna.tf32.f32 %0, %1;" : "=r"(u) : "f"(x)); return u;
}
__device__ __forceinline__ float f2tf_f(float x){ return __uint_as_float(f2tf(x)); }

__device__ __forceinline__ void mma8(float* c, const unsigned* a, const unsigned* b){
    asm volatile("mma.sync.aligned.m16n8k8.row.col.f32.tf32.tf32.f32 "
        "{%0,%1,%2,%3}, {%4,%5,%6,%7}, {%8,%9}, {%0,%1,%2,%3};\n"
        : "+f"(c[0]), "+f"(c[1]), "+f"(c[2]), "+f"(c[3])
        : "r"(a[0]), "r"(a[1]), "r"(a[2]), "r"(a[3]), "r"(b[0]), "r"(b[1]));
}

// cp.async helpers (16B, L2-targeted)
__device__ __forceinline__ void cpa16(uint32_t dst, const void* src){
    asm volatile("cp.async.cg.shared.global [%0], [%1], 16;\n" :: "r"(dst), "l"(src));
}
__device__ __forceinline__ void cpa_commit(){ asm volatile("cp.async.commit_group;\n" ::: "memory"); }
template<int N> __device__ __forceinline__ void cpa_wait(){
    asm volatile("cp.async.wait_group %0;\n" :: "n"(N) : "memory");
}

// ---------------------------------------------------------------------------
// TF32 GEMM: C[4096,1024] = A @ W + bias.  Block tile 128x128, BK=16,
// 256 threads (8 warps 2x4, warp 64x32). 3-stage cp.async pipeline, raw f32
// smem, tf32 cvt at fragment load. 1 barrier per k-iter.
// Smem strides chosen conflict-free for both cp.async stores & frag LDS:
//   A[m][28] (data cols 0..15), B[k][136] (data cols 0..127).
// ---------------------------------------------------------------------------
#define GA_STRIDE 28
#define GB_STRIDE 136
#define G_ASZ (128*GA_STRIDE)              // 3584 floats
#define G_BSZ (16*GB_STRIDE)               // 2176 floats
#define G_STAGE (G_ASZ + G_BSZ)            // 5760 floats = 23040 B
#define G_SMEM_BYTES (3*G_STAGE*4)         // 69120 B

__device__ __forceinline__ void gemm_body(
    const float* __restrict__ A, const float* __restrict__ W,
    const float* __restrict__ bias, float* __restrict__ C, float* sm)
{
    const int N = 1024, K = 1024;
    uint32_t smb = (uint32_t)__cvta_generic_to_shared(sm);

    int tid  = threadIdx.x;
    int lane = tid & 31, warp = tid >> 5;
    int g = lane >> 2, tg = lane & 3;
    int wm = (warp & 1) * 64;
    int wn = (warp >> 1) * 32;
    int row0 = blockIdx.y * 128;
    int col0 = blockIdx.x * 128;

    float acc[4][4][4];
    #pragma unroll
    for (int mi = 0; mi < 4; mi++)
        #pragma unroll
        for (int ni = 0; ni < 4; ni++)
            #pragma unroll
            for (int r = 0; r < 4; r++) acc[mi][ni][r] = 0.f;

    auto load_stage = [&](int i, int s){
        int k0 = i * 16;
        uint32_t ab = smb + (uint32_t)(s * G_STAGE) * 4u;
        uint32_t bbase = ab + (uint32_t)G_ASZ * 4u;
        #pragma unroll
        for (int j = 0; j < 2; j++) {
            int idx = tid + 256*j;
            int ra = idx >> 2;           // 0..127
            int kq = (idx & 3) << 2;     // 0,4,8,12
            cpa16(ab + (uint32_t)(ra*GA_STRIDE + kq)*4u,
                  A + (size_t)(row0+ra)*K + k0 + kq);
            int rb = idx >> 5;           // 0..15
            int nq = (idx & 31) << 2;    // 0..124
            cpa16(bbase + (uint32_t)(rb*GB_STRIDE + nq)*4u,
                  W + (size_t)(k0+rb)*N + col0 + nq);
        }
        cpa_commit();
    };

    load_stage(0, 0);
    load_stage(1, 1);

    for (int i = 0; i < 64; i++) {
        cpa_wait<1>();
        __syncthreads();                     // stage i visible; compute i-1 finished
        if (i + 2 < 64) load_stage(i + 2, (i + 2) % 3);

        const float* As = sm + (i % 3) * G_STAGE;
        const float* Bs = As + G_ASZ;

        #pragma unroll
        for (int ks = 0; ks < 2; ks++) {
            int kk = ks * 8;
            unsigned a[4][4], b[4][2];
            #pragma unroll
            for (int mi = 0; mi < 4; mi++) {
                int m = wm + mi*16;
                a[mi][0] = f2tf(As[(m+g  )*GA_STRIDE + kk+tg  ]);
                a[mi][1] = f2tf(As[(m+g+8)*GA_STRIDE + kk+tg  ]);
                a[mi][2] = f2tf(As[(m+g  )*GA_STRIDE + kk+tg+4]);
                a[mi][3] = f2tf(As[(m+g+8)*GA_STRIDE + kk+tg+4]);
            }
            #pragma unroll
            for (int ni = 0; ni < 4; ni++) {
                int n = wn + ni*8;
                b[ni][0] = f2tf(Bs[(kk+tg  )*GB_STRIDE + n+g]);
                b[ni][1] = f2tf(Bs[(kk+tg+4)*GB_STRIDE + n+g]);
            }
            #pragma unroll
            for (int mi = 0; mi < 4; mi++)
                #pragma unroll
                for (int ni = 0; ni < 4; ni++)
                    mma8(acc[mi][ni], a[mi], b[ni]);
        }
    }

    #pragma unroll
    for (int mi = 0; mi < 4; mi++) {
        int r = row0 + wm + mi*16 + g;
        #pragma unroll
        for (int ni = 0; ni < 4; ni++) {
            int c = col0 + wn + ni*8 + 2*tg;
            float b0 = bias[c], b1 = bias[c+1];
            C[(size_t)r*N + c]       = acc[mi][ni][0] + b0;
            C[(size_t)r*N + c+1]     = acc[mi][ni][1] + b1;
            C[(size_t)(r+8)*N + c]   = acc[mi][ni][2] + b0;
            C[(size_t)(r+8)*N + c+1] = acc[mi][ni][3] + b1;
        }
    }
}

__global__ __launch_bounds__(256, 2)
void proj3_kernel(const float* __restrict__ q, const float* __restrict__ k,
                  const float* __restrict__ v,
                  const float* __restrict__ wq, const float* __restrict__ bq,
                  const float* __restrict__ wk, const float* __restrict__ bk,
                  const float* __restrict__ wv, const float* __restrict__ bv)
{
    extern __shared__ float sm[];
    if (blockIdx.z == 0)      gemm_body(q, wq, bq, g_q, sm);
    else if (blockIdx.z == 1) gemm_body(k, wk, bk, g_k, sm);
    else                      gemm_body(v, wv, bv, g_v, sm);
}

__global__ __launch_bounds__(256, 2)
void out_kernel(const float* __restrict__ wo, const float* __restrict__ bo,
                float* __restrict__ out)
{
    extern __shared__ float sm[];
    gemm_body(g_o, wo, bo, out, sm);
}

// ---------------------------------------------------------------------------
// Flash attention: grid (32 q-tiles, 32 b*h), 128 threads (4 warps x 16 rows).
// K/V tiles of 64 double-buffered via cp.async (raw f32, cvt at frag load).
// logits = (Q.K)/64 + (1-mask)*(-1.25e9); online softmax; O = P.V / l.
// Smem: QP 64x68 | KV buf0 (K 64x68, V 64x68) | KV buf1 | mask 2x64
// ---------------------------------------------------------------------------
#define AT_STRIDE 68
#define AT_QP   (64*AT_STRIDE)             // 4352 floats
#define AT_KV   (64*AT_STRIDE)             // per K or V tile
#define AT_BUF  (2*AT_KV)                  // 8704 floats
#define AT_SMEM_FLOATS (AT_QP + 2*AT_BUF + 2*64)   // 21888 -> 87552 B

__global__ __launch_bounds__(128)
void attn_kernel(const float* __restrict__ mask)
{
    extern __shared__ float sm[];
    float* QP = sm;                          // Q raw, later reused as P
    float* mskbuf = sm + AT_QP + 2*AT_BUF;   // 2 x 64
    uint32_t smb = (uint32_t)__cvta_generic_to_shared(sm);
    uint32_t qpb = smb;
    uint32_t mb  = smb + (uint32_t)(AT_QP + 2*AT_BUF)*4u;

    int tid = threadIdx.x, lane = tid & 31, warp = tid >> 5;
    int g = lane >> 2, tg = lane & 3;
    int q0 = blockIdx.x * 64;
    int b  = blockIdx.y >> 4, h = blockIdx.y & 15;
    int wrow = warp * 16;

    const float* Qg = g_q + (size_t)b*Ss*Hh + h*HDIM;
    const float* Kg = g_k + (size_t)b*Ss*Hh + h*HDIM;
    const float* Vg = g_v + (size_t)b*Ss*Hh + h*HDIM;
    const float* mrow = mask + (size_t)b*Ss;

    auto stage_kv = [&](int kt, int s){
        uint32_t kb = smb + (uint32_t)(AT_QP + s*AT_BUF)*4u;
        uint32_t vb = kb + (uint32_t)AT_KV*4u;
        #pragma unroll
        for (int j = 0; j < 8; j++) {
            int idx = tid + 128*j;           // 0..1023
            int r = idx >> 4, dq = (idx & 15) << 2;
            cpa16(kb + (uint32_t)(r*AT_STRIDE + dq)*4u,
                  Kg + (size_t)(kt*64+r)*Hh + dq);
            cpa16(vb + (uint32_t)(r*AT_STRIDE + dq)*4u,
                  Vg + (size_t)(kt*64+r)*Hh + dq);
        }
        if (tid < 16)
            cpa16(mb + (uint32_t)(s*64 + tid*4)*4u, mrow + kt*64 + tid*4);
        cpa_commit();
    };

    // Stage Q raw (group 1), then KV tile 0 (group 2)
    #pragma unroll
    for (int j = 0; j < 8; j++) {
        int idx = tid + 128*j;               // 0..1023
        int r = idx >> 4, dq = (idx & 15) << 2;
        cpa16(qpb + (uint32_t)(r*AT_STRIDE + dq)*4u,
              Qg + (size_t)(q0+r)*Hh + dq);
    }
    cpa_commit();
    stage_kv(0, 0);

    cpa_wait<1>();                           // Q arrived
    __syncthreads();

    // Extract Q fragments, both /SCALE divisions folded in (1/64)
    unsigned qa[8][4];
    #pragma unroll
    for (int kk = 0; kk < 8; kk++) {
        qa[kk][0] = f2tf(QP[(wrow+g  )*AT_STRIDE + kk*8+tg  ] * 0.015625f);
        qa[kk][1] = f2tf(QP[(wrow+g+8)*AT_STRIDE + kk*8+tg  ] * 0.015625f);
        qa[kk][2] = f2tf(QP[(wrow+g  )*AT_STRIDE + kk*8+tg+4] * 0.015625f);
        qa[kk][3] = f2tf(QP[(wrow+g+8)*AT_STRIDE + kk*8+tg+4] * 0.015625f);
    }
    float* Ps = QP;   // reuse (per-warp row ownership; ordered by loop barriers)

    float oc[8][4];
    #pragma unroll
    for (int ni = 0; ni < 8; ni++)
        #pragma unroll
        for (int r = 0; r < 4; r++) oc[ni][r] = 0.f;

    float m0 = -1e30f, m1 = -1e30f, l0 = 0.f, l1 = 0.f;

    for (int kt = 0; kt < 32; kt++) {
        if (kt + 1 < 32) { stage_kv(kt+1, (kt+1)&1); cpa_wait<1>(); }
        else             { cpa_wait<0>(); }
        __syncthreads();                     // tile kt visible everywhere

        const float* Ks = sm + AT_QP + (kt&1)*AT_BUF;
        const float* Vs = Ks + AT_KV;
        const float* msk = mskbuf + (kt&1)*64;

        // S = Qscaled . K^T
        float sc[8][4];
        #pragma unroll
        for (int ni = 0; ni < 8; ni++)
            #pragma unroll
            for (int r = 0; r < 4; r++) sc[ni][r] = 0.f;
        #pragma unroll
        for (int kk = 0; kk < 8; kk++) {
            #pragma unroll
            for (int ni = 0; ni < 8; ni++) {
                unsigned bb[2];
                bb[0] = f2tf(Ks[(ni*8+g)*AT_STRIDE + kk*8+tg  ]);
                bb[1] = f2tf(Ks[(ni*8+g)*AT_STRIDE + kk*8+tg+4]);
                mma8(sc[ni], qa[kk], bb);
            }
        }
        // additive mask: (1-m)*(-1e10)/8
        #pragma unroll
        for (int ni = 0; ni < 8; ni++) {
            int c = ni*8 + 2*tg;
            float w0 = (1.0f - msk[c  ]) * (-1.25e9f);
            float w1 = (1.0f - msk[c+1]) * (-1.25e9f);
            sc[ni][0] += w0; sc[ni][1] += w1;
            sc[ni][2] += w0; sc[ni][3] += w1;
        }
        // Online softmax (rows g and g+8; reduce over tg lanes)
        float tm0 = -1e30f, tm1 = -1e30f;
        #pragma unroll
        for (int ni = 0; ni < 8; ni++) {
            tm0 = fmaxf(tm0, fmaxf(sc[ni][0], sc[ni][1]));
            tm1 = fmaxf(tm1, fmaxf(sc[ni][2], sc[ni][3]));
        }
        tm0 = fmaxf(tm0, __shfl_xor_sync(0xffffffffu, tm0, 1));
        tm0 = fmaxf(tm0, __shfl_xor_sync(0xffffffffu, tm0, 2));
        tm1 = fmaxf(tm1, __shfl_xor_sync(0xffffffffu, tm1, 1));
        tm1 = fmaxf(tm1, __shfl_xor_sync(0xffffffffu, tm1, 2));
        float nm0 = fmaxf(m0, tm0), nm1 = fmaxf(m1, tm1);
        float al0 = __expf(m0 - nm0), al1 = __expf(m1 - nm1);
        float rs0 = 0.f, rs1 = 0.f;
        #pragma unroll
        for (int ni = 0; ni < 8; ni++) {
            float p0 = __expf(sc[ni][0] - nm0);
            float p1 = __expf(sc[ni][1] - nm0);
            float p2 = __expf(sc[ni][2] - nm1);
            float p3 = __expf(sc[ni][3] - nm1);
            rs0 += p0 + p1; rs1 += p2 + p3;
            int c = ni*8 + 2*tg;
            Ps[(wrow+g  )*AT_STRIDE + c  ] = f2tf_f(p0);
            Ps[(wrow+g  )*AT_STRIDE + c+1] = f2tf_f(p1);
            Ps[(wrow+g+8)*AT_STRIDE + c  ] = f2tf_f(p2);
            Ps[(wrow+g+8)*AT_STRIDE + c+1] = f2tf_f(p3);
            oc[ni][0] *= al0; oc[ni][1] *= al0;
            oc[ni][2] *= al1; oc[ni][3] *= al1;
        }
        rs0 += __shfl_xor_sync(0xffffffffu, rs0, 1);
        rs0 += __shfl_xor_sync(0xffffffffu, rs0, 2);
        rs1 += __shfl_xor_sync(0xffffffffu, rs1, 1);
        rs1 += __shfl_xor_sync(0xffffffffu, rs1, 2);
        l0 = l0*al0 + rs0;  l1 = l1*al1 + rs1;
        m0 = nm0;  m1 = nm1;
        __syncwarp();

        // O += P . V  (each warp reads only its own P rows)
        #pragma unroll
        for (int kk = 0; kk < 8; kk++) {
            unsigned pa[4];
            pa[0] = __float_as_uint(Ps[(wrow+g  )*AT_STRIDE + kk*8+tg  ]);
            pa[1] = __float_as_uint(Ps[(wrow+g+8)*AT_STRIDE + kk*8+tg  ]);
            pa[2] = __float_as_uint(Ps[(wrow+g  )*AT_STRIDE + kk*8+tg+4]);
            pa[3] = __float_as_uint(Ps[(wrow+g+8)*AT_STRIDE + kk*8+tg+4]);
            #pragma unroll
            for (int ni = 0; ni < 8; ni++) {
                unsigned bb[2];
                bb[0] = f2tf(Vs[(kk*8+tg  )*AT_STRIDE + ni*8+g]);
                bb[1] = f2tf(Vs[(kk*8+tg+4)*AT_STRIDE + ni*8+g]);
                mma8(oc[ni], pa, bb);
            }
        }
        __syncthreads();   // all reads of buf done before it is re-staged
    }

    float inv0 = 1.f / l0, inv1 = 1.f / l1;
    float* Og = g_o + (size_t)b*Ss*Hh + h*HDIM;
    #pragma unroll
    for (int ni = 0; ni < 8; ni++) {
        int c = ni*8 + 2*tg;
        int r = q0 + wrow + g;
        Og[(size_t)r*Hh + c]       = oc[ni][0] * inv0;
        Og[(size_t)r*Hh + c+1]     = oc[ni][1] * inv0;
        Og[(size_t)(r+8)*Hh + c]   = oc[ni][2] * inv1;
        Og[(size_t)(r+8)*Hh + c+1] = oc[ni][3] * inv1;
    }
}

// ---------------------------------------------------------------------------
extern "C" void kernel_launch(void* const* d_in, const int* in_sizes, int n_in,
                              void* d_out, int out_size)
{
    const float* query = (const float*)d_in[0];
    const float* key   = (const float*)d_in[1];
    const float* value = (const float*)d_in[2];
    const float* mask  = (const float*)d_in[3];
    const float* wq    = (const float*)d_in[4];
    const float* bq    = (const float*)d_in[5];
    const float* wk    = (const float*)d_in[6];
    const float* bk    = (const float*)d_in[7];
    const float* wv    = (const float*)d_in[8];
    const float* bv    = (const float*)d_in[9];
    const float* wo    = (const float*)d_in[10];
    const float* bo    = (const float*)d_in[11];

    const int gemm_smem = G_SMEM_BYTES;                       // 69120 B
    const int attn_smem = AT_SMEM_FLOATS * (int)sizeof(float); // 87552 B
    cudaFuncSetAttribute(proj3_kernel, cudaFuncAttributeMaxDynamicSharedMemorySize, gemm_smem);
    cudaFuncSetAttribute(out_kernel,   cudaFuncAttributeMaxDynamicSharedMemorySize, gemm_smem);
    cudaFuncSetAttribute(attn_kernel,  cudaFuncAttributeMaxDynamicSharedMemorySize, attn_smem);

    proj3_kernel<<<dim3(8, 32, 3), 256, gemm_smem>>>(query, key, value, wq, bq, wk, bk, wv, bv);
    attn_kernel<<<dim3(32, 32), 128, attn_smem>>>(mask);
    out_kernel<<<dim3(8, 32), 256, gemm_smem>>>(wo, bo, (float*)d_out);
}